// round 12
// baseline (speedup 1.0000x reference)
#include <cuda_runtime.h>
#include <cstdint>

#define RB 16
#define NC 80
#define NB 16
#define NA 8400
#define CHN 144
#define KP 1024
#define MAXDET 300
#define CONF 0.25f
#define IOUT 0.45f
#define GRID_PAD 160

// ---------------- scratch (no allocations allowed) ----------------
__device__ float4 g_boxes[NB * NA];
__device__ unsigned long long g_keys[NB * NA];

__device__ __forceinline__ int read_dim(const int* p) {
    if (!p) return 640;
    int v = *p;
    if (v > 0 && v < 100000) return v;
    float f = __int_as_float(v);
    return (int)f;
}

__device__ __forceinline__ float f4c(const float4& f, int j) {
    return (j == 0) ? f.x : (j == 1) ? f.y : (j == 2) ? f.z : f.w;
}

// ---------------- Phase A: decode (validated r11 form; at HBM roofline) -----------
__global__ __launch_bounds__(128) void decode_k(const float* __restrict__ p0,
                                                const float* __restrict__ p1,
                                                const float* __restrict__ p2,
                                                const int* pH, const int* pW) {
    int gid = blockIdx.x * blockDim.x + threadIdx.x;
    const int tot = NB * NA / 4;
    if (gid >= tot) return;
    int b = gid / (NA / 4);
    int a4 = (gid - b * (NA / 4)) * 4;

    const float* p; int W, stride, lb, HW;
    if (a4 < 6400)      { p = p0; W = 80; stride = 8;  lb = 0;    HW = 6400; }
    else if (a4 < 8000) { p = p1; W = 40; stride = 16; lb = 6400; HW = 1600; }
    else                { p = p2; W = 20; stride = 32; lb = 8000; HW = 400;  }
    int hw = a4 - lb;
    int HW4 = HW >> 2;
    const float4* base = (const float4*)(p + (size_t)b * CHN * HW) + (hw >> 2);

    float4 dd[4];
    #pragma unroll
    for (int k = 0; k < 4; k++) {
        float4 v[RB];
        #pragma unroll
        for (int r = 0; r < RB; r++) v[r] = base[(size_t)(k * RB + r) * HW4];
        float4 mx = make_float4(-1e30f, -1e30f, -1e30f, -1e30f);
        #pragma unroll
        for (int r = 0; r < RB; r++) {
            mx.x = fmaxf(mx.x, v[r].x); mx.y = fmaxf(mx.y, v[r].y);
            mx.z = fmaxf(mx.z, v[r].z); mx.w = fmaxf(mx.w, v[r].w);
        }
        float4 s = make_float4(0.f, 0.f, 0.f, 0.f);
        float4 ws = make_float4(0.f, 0.f, 0.f, 0.f);
        #pragma unroll
        for (int r = 0; r < RB; r++) {
            float fr = (float)r;
            float ex = expf(v[r].x - mx.x); s.x += ex; ws.x += ex * fr;
            float ey = expf(v[r].y - mx.y); s.y += ey; ws.y += ey * fr;
            float ez = expf(v[r].z - mx.z); s.z += ez; ws.z += ez * fr;
            float ew = expf(v[r].w - mx.w); s.w += ew; ws.w += ew * fr;
        }
        float st = (float)stride;
        dd[k].x = ws.x / s.x * st; dd[k].y = ws.y / s.y * st;
        dd[k].z = ws.z / s.z * st; dd[k].w = ws.w / s.w * st;
    }

    float4 mx2 = base[(size_t)64 * HW4];
    int lab[4] = {0, 0, 0, 0};
    #pragma unroll 8
    for (int c = 1; c < NC; c++) {
        float4 z = base[(size_t)(64 + c) * HW4];
        if (z.x > mx2.x) { mx2.x = z.x; lab[0] = c; }
        if (z.y > mx2.y) { mx2.y = z.y; lab[1] = c; }
        if (z.z > mx2.z) { mx2.z = z.z; lab[2] = c; }
        if (z.w > mx2.w) { mx2.w = z.w; lab[3] = c; }
    }

    int himg = read_dim(pH), wimg = read_dim(pW);
    float hiW = (float)(wimg - 1), hiH = (float)(himg - 1);
    float st = (float)stride;
    int y0 = hw / W, x0 = hw % W;
    float cy = ((float)y0 + 0.5f) * st;

    #pragma unroll
    for (int j = 0; j < 4; j++) {
        float dl = f4c(dd[0], j), dt = f4c(dd[1], j);
        float dr = f4c(dd[2], j), db = f4c(dd[3], j);
        float mxc = f4c(mx2, j);
        int   lbl = lab[j];
        float cx = ((float)(x0 + j) + 0.5f) * st;
        float x1 = fminf(fmaxf(cx - dl, 0.f), hiW);
        float y1 = fminf(fmaxf(cy - dt, 0.f), hiH);
        float x2 = fminf(fmaxf(cx + dr, 0.f), hiW);
        float y2 = fminf(fmaxf(cy + db, 0.f), hiH);
        int g = b * NA + a4 + j;
        g_boxes[g] = make_float4(x1, y1, x2, y2);
        float sc = 1.0f / (1.0f + expf(-mxc));
        float sp = (sc > CONF) ? sc : -1.0f;
        unsigned u = __float_as_uint(sp);
        u = (u & 0x80000000u) ? ~u : (u | 0x80000000u);
        unsigned hi = ~u;                 // MSB clear <=> score passed conf
        g_keys[g] = ((unsigned long long)hi << 32)
                  | (unsigned)(((a4 + j) << 7) | lbl);
    }
}

// ---------------- Phase B smem (dynamic) ------------------
struct SmemT {
    unsigned long long gath[KP];
    unsigned long long kkey[KP];
    unsigned long long mini[64];
    unsigned long long warr[MAXDET];
    unsigned long long s_thr;
    unsigned int hist[2048];
    float4 sbox[KP];
    short  kidx[KP];
    short  widx[MAXDET];
    short  mem[NC][64];
    unsigned char skeep[KP];
    int ccnt[NC];
    int srank[MAXDET];
    int wsum[33];
    unsigned int wtot[32];
    int s_b, s_rank, s_cnt, s_gcnt, s_mcnt;
};

__device__ __forceinline__ void hist_scan_resolve(SmemT& S, int tid, int w, int lane,
                                                  unsigned rank_) {
    const unsigned full = 0xFFFFFFFFu;
    unsigned e0 = S.hist[2 * tid], e1 = S.hist[2 * tid + 1];
    unsigned incl = e0 + e1;
    #pragma unroll
    for (int o = 1; o < 32; o <<= 1) {
        unsigned t = __shfl_up_sync(full, incl, o);
        if (lane >= o) incl += t;
    }
    if (lane == 31) S.wtot[w] = incl;
    __syncthreads();
    if (w == 0) {
        unsigned v = S.wtot[lane], iv = v;
        #pragma unroll
        for (int o = 1; o < 32; o <<= 1) {
            unsigned t = __shfl_up_sync(full, iv, o);
            if (lane >= o) iv += t;
        }
        S.wtot[lane] = iv - v;
    }
    __syncthreads();
    unsigned incl1 = S.wtot[w] + incl;
    unsigned incl0 = incl1 - e1;
    unsigned excl0 = incl0 - e0, excl1 = incl1 - e1;
    if (e0 && excl0 < rank_ && rank_ <= incl0) { S.s_b = 2 * tid;     S.s_rank = (int)(rank_ - excl0); S.s_cnt = (int)e0; }
    if (e1 && excl1 < rank_ && rank_ <= incl1) { S.s_b = 2 * tid + 1; S.s_rank = (int)(rank_ - excl1); S.s_cnt = (int)e1; }
    __syncthreads();
}

__global__ __launch_bounds__(1024) void topk_nms_k(float* __restrict__ out) {
    if (blockIdx.x >= NB) return;
    extern __shared__ unsigned char dynraw[];
    SmemT& S = *reinterpret_cast<SmemT*>(dynraw);

    int b = blockIdx.x, tid = threadIdx.x, w = tid >> 5, lane = tid & 31;
    const unsigned full = 0xFFFFFFFFu;
    unsigned lt = (1u << lane) - 1u;
    const unsigned long long* keys = g_keys + (size_t)b * NA;
    const int shifts[6] = {53, 42, 31, 20, 9, 0};

    // register-cache all 9 strided keys once; reused by every pass + the gather
    unsigned long long kv[9];
    #pragma unroll
    for (int n = 0; n < 9; n++) {
        int i = tid + n * 1024;
        kv[n] = (i < NA) ? keys[i] : 0xFFFFFFFFFFFFFFFFull;
    }
    const bool v8 = (tid < NA - 8192);           // validity of kv[8]

    // ===== 1. radix select (validated logic; register-resident sweeps) =====
    unsigned long long prefix = 0, pmask = 0;
    int rank = KP;
    #pragma unroll 1
    for (int pass = 0; pass < 6; pass++) {
        int sh = shifts[pass];
        unsigned bm = (pass == 5) ? 511u : 2047u;
        S.hist[tid] = 0; S.hist[tid + 1024] = 0;
        __syncthreads();
        #pragma unroll
        for (int n = 0; n < 9; n++) {
            bool valid = (n < 8) || v8;
            unsigned long long k = kv[n];
            if (valid && (k & pmask) == prefix)
                atomicAdd(&S.hist[(unsigned)(k >> sh) & bm], 1u);
        }
        __syncthreads();
        hist_scan_resolve(S, tid, w, lane, (unsigned)rank);
        prefix |= ((unsigned long long)(unsigned)S.s_b) << sh;
        pmask  |= ((unsigned long long)bm) << sh;
        rank = S.s_rank;
        if (S.s_cnt <= 64) break;
    }
    int bcnt = S.s_cnt, brank = rank;
    int below = KP - brank;

    // ===== 2. gather 1024 candidates + fused box staging =====
    if (tid == 0) { S.s_gcnt = 0; S.s_mcnt = 0; }
    if (tid < NC) S.ccnt[tid] = 0;
    __syncthreads();
    #pragma unroll 1
    for (int n2 = 0; n2 < 9; n2++) {
        bool valid = (n2 < 8) || v8;
        unsigned long long k = kv[n2];
        unsigned long long masked = valid ? (k & pmask) : ~0ull;
        bool vlo = (masked < prefix);
        bool vm  = (masked == prefix) && valid;
        unsigned blo = __ballot_sync(full, vlo);
        unsigned bmk = __ballot_sync(full, vm);
        int base = 0, base2 = 0;
        if (lane == 0) {
            if (blo) base  = atomicAdd(&S.s_gcnt, __popc(blo));
            if (bmk) base2 = atomicAdd(&S.s_mcnt, __popc(bmk));
        }
        base  = __shfl_sync(full, base, 0);
        base2 = __shfl_sync(full, base2, 0);
        if (vlo) {
            int pos = base + __popc(blo & lt);
            S.gath[pos] = k;
            S.sbox[pos] = g_boxes[b * NA + (int)((unsigned)(k & 0xFFFFFFFFu) >> 7)];
        }
        if (vm)  S.mini[base2 + __popc(bmk & lt)] = k;
    }
    __syncthreads();
    if (tid < bcnt) {
        unsigned long long m = S.mini[tid];
        int r = 0;
        for (int j = 0; j < bcnt; j++) r += (S.mini[j] < m);
        if (r < brank) {
            S.gath[below + r] = m;
            S.sbox[below + r] = g_boxes[b * NA + (int)((unsigned)(m & 0xFFFFFFFFu) >> 7)];
        }
    }
    __syncthreads();

    // ===== 3+4a. per-candidate key fields + member lists (arbitrary order) =====
    unsigned long long mykey = S.gath[tid];
    unsigned klo = (unsigned)(mykey & 0xFFFFFFFFu);
    unsigned khi = (unsigned)(mykey >> 32);
    int myc = (int)(klo & 127u);
    bool act = ((int)khi >= 0);                  // MSB clear <=> conf-passing
    S.skeep[tid] = 0;
    if (act) {
        int mypos = atomicAdd(&S.ccnt[myc], 1);
        if (mypos < 64) S.mem[myc][mypos] = (short)tid;
    }
    __syncthreads();

    // ===== 4c. NMS: in-warp rank sort + adjacency-bitmask chains =====
    for (int c = w; c < NC; c += 32) {
        int cnt = min(S.ccnt[c], 64);
        if (cnt == 0) continue;
        short* mem = S.mem[c];
        float off = (float)c * 4096.0f;

        if (cnt <= 32) {
            int mi = (lane < cnt) ? mem[lane] : -1;
            unsigned long long kk = (mi >= 0) ? S.gath[mi] : ~0ull;
            // exact rank among members (unique keys) via uniform shfl loop
            int r = 0;
            #pragma unroll 4
            for (int j = 0; j < cnt; j++) {
                unsigned long long kj = __shfl_sync(full, kk, j);
                if (lane < cnt && kj < kk) r++;
            }
            // invert the permutation: src = lane holding rank == my lane id
            int src = 0;
            #pragma unroll 4
            for (int j = 0; j < cnt; j++) {
                int rj = __shfl_sync(full, r, j);
                if (rj == lane) src = j;
            }
            int mis = __shfl_sync(full, mi, src);   // member idx, sorted by key
            float4 bb = make_float4(0.f, 0.f, 0.f, 0.f);
            float ar = 0.f;
            if (lane < cnt) {
                float4 t = S.sbox[mis];
                bb = make_float4(__fadd_rn(t.x, off), __fadd_rn(t.y, off),
                                 __fadd_rn(t.z, off), __fadd_rn(t.w, off));
                ar = __fmul_rn(__fsub_rn(bb.z, bb.x), __fsub_rn(bb.w, bb.y));
            }
            // adjacency rows (validated r11 math)
            unsigned adj = 0;
            #pragma unroll 4
            for (int j = 0; j < cnt; j++) {
                float bx = __shfl_sync(full, bb.x, j);
                float by = __shfl_sync(full, bb.y, j);
                float bz = __shfl_sync(full, bb.z, j);
                float bw = __shfl_sync(full, bb.w, j);
                float aj = __shfl_sync(full, ar, j);
                if (j < lane && lane < cnt) {
                    float lx = fmaxf(bb.x, bx), ly = fmaxf(bb.y, by);
                    float rx = fminf(bb.z, bz), ry = fminf(bb.w, bw);
                    float iw = fmaxf(__fsub_rn(rx, lx), 0.f);
                    float ih = fmaxf(__fsub_rn(ry, ly), 0.f);
                    float inter = __fmul_rn(iw, ih);
                    float den = __fadd_rn(__fsub_rn(__fadd_rn(aj, ar), inter), 1e-7f);
                    if (__fdiv_rn(inter, den) > IOUT) adj |= 1u << j;
                }
            }
            unsigned km = 0;
            #pragma unroll 4
            for (int i = 0; i < cnt; i++) {
                unsigned a = __shfl_sync(full, adj, i);
                if ((a & km) == 0u) km |= 1u << i;
            }
            if (lane < cnt && ((km >> lane) & 1u)) S.skeep[mis] = 1;
        } else {
            // rare fallback: warp-local sort then validated 2-slot ballot chain
            int m0 = (lane < cnt) ? mem[lane] : -1;
            int m1 = (lane + 32 < cnt) ? mem[lane + 32] : -1;
            unsigned long long k0 = (m0 >= 0) ? S.gath[m0] : ~0ull;
            unsigned long long k1 = (m1 >= 0) ? S.gath[m1] : ~0ull;
            int r0 = 0, r1 = 0;
            for (int j = 0; j < cnt; j++) {
                unsigned long long kj = S.gath[mem[j]];
                r0 += (kj < k0); r1 += (kj < k1);
            }
            __syncwarp();
            if (m0 >= 0) mem[r0] = (short)m0;
            if (m1 >= 0) mem[r1] = (short)m1;
            __syncwarp();
            m0 = (lane < cnt) ? mem[lane] : -1;
            m1 = (lane + 32 < cnt) ? mem[lane + 32] : -1;
            float4 b0 = make_float4(0.f, 0.f, 0.f, 0.f), b1 = b0;
            float ar0 = 0.f, ar1 = 0.f;
            if (m0 >= 0) {
                float4 t = S.sbox[m0];
                b0 = make_float4(__fadd_rn(t.x, off), __fadd_rn(t.y, off),
                                 __fadd_rn(t.z, off), __fadd_rn(t.w, off));
                ar0 = __fmul_rn(__fsub_rn(b0.z, b0.x), __fsub_rn(b0.w, b0.y));
            }
            if (m1 >= 0) {
                float4 t = S.sbox[m1];
                b1 = make_float4(__fadd_rn(t.x, off), __fadd_rn(t.y, off),
                                 __fadd_rn(t.z, off), __fadd_rn(t.w, off));
                ar1 = __fmul_rn(__fsub_rn(b1.z, b1.x), __fsub_rn(b1.w, b1.y));
            }
            bool sup0 = false, sup1 = false;
            #pragma unroll 1
            for (int i = 0; i < cnt; i++) {
                int d = i >> 5, l = i & 31;
                unsigned sb = __ballot_sync(full, d ? sup1 : sup0);
                bool keep_i = ((sb >> l) & 1u) == 0u;
                if (keep_i) {
                    float bcx = __shfl_sync(full, d ? b1.x : b0.x, l);
                    float bcy = __shfl_sync(full, d ? b1.y : b0.y, l);
                    float bcz = __shfl_sync(full, d ? b1.z : b0.z, l);
                    float bcw = __shfl_sync(full, d ? b1.w : b0.w, l);
                    float ac  = __shfl_sync(full, d ? ar1 : ar0, l);
                    if (m0 >= 0) {
                        float lx = fmaxf(bcx, b0.x), ly = fmaxf(bcy, b0.y);
                        float rx = fminf(bcz, b0.z), ry = fminf(bcw, b0.w);
                        float iw = fmaxf(__fsub_rn(rx, lx), 0.f);
                        float ih = fmaxf(__fsub_rn(ry, ly), 0.f);
                        float inter = __fmul_rn(iw, ih);
                        float den = __fadd_rn(__fsub_rn(__fadd_rn(ac, ar0), inter), 1e-7f);
                        if (__fdiv_rn(inter, den) > IOUT) sup0 = true;
                    }
                    if (m1 >= 0) {
                        float lx = fmaxf(bcx, b1.x), ly = fmaxf(bcy, b1.y);
                        float rx = fminf(bcz, b1.z), ry = fminf(bcw, b1.w);
                        float iw = fmaxf(__fsub_rn(rx, lx), 0.f);
                        float ih = fmaxf(__fsub_rn(ry, ly), 0.f);
                        float inter = __fmul_rn(iw, ih);
                        float den = __fadd_rn(__fsub_rn(__fadd_rn(ac, ar1), inter), 1e-7f);
                        if (__fdiv_rn(inter, den) > IOUT) sup1 = true;
                    }
                    if (lane == l) {
                        if (d) S.skeep[m1] = 1; else S.skeep[m0] = 1;
                    }
                }
            }
        }
    }
    __syncthreads();

    // ===== 5. compact kept candidates =====
    int kv2 = S.skeep[tid];
    unsigned bal2 = __ballot_sync(full, kv2 != 0);
    int wpre = __popc(bal2 & lt);
    if (lane == 0) S.wsum[w] = __popc(bal2);
    __syncthreads();
    if (w == 0) {
        int vv = S.wsum[lane], orig = vv;
        #pragma unroll
        for (int o = 1; o < 32; o <<= 1) {
            int t = __shfl_up_sync(full, vv, o);
            if (lane >= o) vv += t;
        }
        S.wsum[lane] = vv - orig;
        if (lane == 31) S.wsum[32] = vv;
    }
    __syncthreads();
    int n_kept = S.wsum[32];
    if (kv2) {
        int pos = S.wsum[w] + wpre;
        S.kkey[pos] = mykey;
        S.kidx[pos] = (short)tid;
    }
    if (tid == 0) S.s_thr = ~0ull;
    __syncthreads();

    // ===== 6. exact 300th-kept-key threshold (smem radix select) =====
    if (n_kept > MAXDET) {
        unsigned long long p2 = 0, m2 = 0;
        int r2 = MAXDET;
        #pragma unroll 1
        for (int pass = 0; pass < 6; pass++) {
            int sh = shifts[pass];
            unsigned bm = (pass == 5) ? 511u : 2047u;
            S.hist[tid] = 0; S.hist[tid + 1024] = 0;
            __syncthreads();
            if (tid < n_kept) {
                unsigned long long k = S.kkey[tid];
                if ((k & m2) == p2)
                    atomicAdd(&S.hist[(unsigned)(k >> sh) & bm], 1u);
            }
            __syncthreads();
            hist_scan_resolve(S, tid, w, lane, (unsigned)r2);
            p2 |= ((unsigned long long)(unsigned)S.s_b) << sh;
            m2 |= ((unsigned long long)bm) << sh;
            r2 = S.s_rank;
            if (S.s_cnt <= 64) break;
        }
        int bc2 = S.s_cnt, br2 = r2;
        if (tid == 0) S.s_mcnt = 0;
        __syncthreads();
        bool vm = (tid < n_kept) && ((S.kkey[tid] & m2) == p2);
        unsigned bmk = __ballot_sync(full, vm);
        int base2 = 0;
        if (lane == 0 && bmk) base2 = atomicAdd(&S.s_mcnt, __popc(bmk));
        base2 = __shfl_sync(full, base2, 0);
        if (vm) S.mini[base2 + __popc(bmk & lt)] = S.kkey[tid];
        __syncthreads();
        if (tid < bc2) {
            unsigned long long m = S.mini[tid];
            int r = 0;
            for (int j = 0; j < bc2; j++) r += (S.mini[j] < m);
            if (r == br2 - 1) S.s_thr = m;
        }
    }
    __syncthreads();
    unsigned long long thr = S.s_thr;

    // ===== 7. compact winners =====
    bool wf = (tid < n_kept) && (S.kkey[tid] <= thr);
    unsigned bw = __ballot_sync(full, wf);
    int wp = __popc(bw & lt);
    if (lane == 0) S.wsum[w] = __popc(bw);
    __syncthreads();
    if (w == 0) {
        int vv = S.wsum[lane], orig = vv;
        #pragma unroll
        for (int o = 1; o < 32; o <<= 1) {
            int t = __shfl_up_sync(full, vv, o);
            if (lane >= o) vv += t;
        }
        S.wsum[lane] = vv - orig;
        if (lane == 31) S.wsum[32] = vv;
    }
    __syncthreads();
    if (wf) {
        int p3 = S.wsum[w] + wp;
        S.warr[p3] = S.kkey[tid];
        S.widx[p3] = S.kidx[tid];
    }
    if (tid < MAXDET) S.srank[tid] = 0;
    __syncthreads();
    int nw = S.wsum[32];

    // ===== 8. exact rank among winners (3 threads/winner) + output =====
    const int OB = 0;
    const int OS = NB * MAXDET * 4;
    const int OL = OS + NB * MAXDET;
    const int OV = OL + NB * MAXDET;

    if (tid < 3 * nw) {
        int i = tid / 3, seg = tid - 3 * i;
        unsigned long long myk = S.warr[i];
        int jb = (seg * nw) / 3, je = ((seg + 1) * nw) / 3;
        int r = 0;
        #pragma unroll 8
        for (int j = jb; j < je; j++) r += (S.warr[j] < myk);
        if (r) atomicAdd(&S.srank[i], r);
    }
    __syncthreads();
    if (tid < nw) {
        int r = S.srank[tid];
        int cand = S.widx[tid];
        unsigned long long wk = S.gath[cand];
        unsigned lo2 = (unsigned)(wk & 0xFFFFFFFFu);
        unsigned hi2 = (unsigned)(wk >> 32);
        unsigned uu = ~hi2;
        unsigned sbits = (uu & 0x80000000u) ? (uu & 0x7FFFFFFFu) : ~uu;
        float4 bx = S.sbox[cand];
        float* ob = out + OB + ((size_t)b * MAXDET + r) * 4;
        ob[0] = bx.x; ob[1] = bx.y; ob[2] = bx.z; ob[3] = bx.w;
        out[OS + b * MAXDET + r] = __uint_as_float(sbits);
        out[OL + b * MAXDET + r] = (float)(lo2 & 127u);
    }
    if (tid < MAXDET) {
        if (tid >= nw) {
            float* ob = out + OB + ((size_t)b * MAXDET + tid) * 4;
            ob[0] = 0.f; ob[1] = 0.f; ob[2] = 0.f; ob[3] = 0.f;
            out[OS + b * MAXDET + tid] = 0.f;
            out[OL + b * MAXDET + tid] = -1.f;
        }
        out[OV + b * MAXDET + tid] = (tid < nw) ? 1.f : 0.f;
    }
}

// ---------------- launch ----------------
extern "C" void kernel_launch(void* const* d_in, const int* in_sizes, int n_in,
                              void* d_out, int out_size) {
    (void)in_sizes; (void)out_size;
    const float* p0 = (const float*)d_in[0];
    const float* p1 = (const float*)d_in[1];
    const float* p2 = (const float*)d_in[2];
    const int* pH = (n_in > 3) ? (const int*)d_in[3] : nullptr;
    const int* pW = (n_in > 4) ? (const int*)d_in[4] : nullptr;

    cudaFuncSetAttribute(topk_nms_k, cudaFuncAttributeMaxDynamicSharedMemorySize,
                         (int)sizeof(SmemT));
    int tot = NB * NA / 4;
    decode_k<<<(tot + 127) / 128, 128>>>(p0, p1, p2, pH, pW);
    topk_nms_k<<<GRID_PAD, 1024, sizeof(SmemT)>>>((float*)d_out);
}

// round 13
// speedup vs baseline: 1.0188x; 1.0188x over previous
#include <cuda_runtime.h>
#include <cstdint>

#define RB 16
#define NC 80
#define NB 16
#define NA 8400
#define CHN 144
#define KP 1024
#define MAXDET 300
#define CONF 0.25f
#define IOUT 0.45f
#define GRID_PAD 160

// ---------------- scratch (no allocations allowed) ----------------
__device__ float4 g_boxes[NB * NA];
__device__ unsigned long long g_keys[NB * NA];

__device__ __forceinline__ int read_dim(const int* p) {
    if (!p) return 640;
    int v = *p;
    if (v > 0 && v < 100000) return v;
    float f = __int_as_float(v);
    return (int)f;
}

__device__ __forceinline__ float f4c(const float4& f, int j) {
    return (j == 0) ? f.x : (j == 1) ? f.y : (j == 2) ? f.z : f.w;
}

// ---------------- Phase A: decode (validated r11 form; at HBM roofline) -----------
__global__ __launch_bounds__(128) void decode_k(const float* __restrict__ p0,
                                                const float* __restrict__ p1,
                                                const float* __restrict__ p2,
                                                const int* pH, const int* pW) {
    int gid = blockIdx.x * blockDim.x + threadIdx.x;
    const int tot = NB * NA / 4;
    if (gid >= tot) return;
    int b = gid / (NA / 4);
    int a4 = (gid - b * (NA / 4)) * 4;

    const float* p; int W, stride, lb, HW;
    if (a4 < 6400)      { p = p0; W = 80; stride = 8;  lb = 0;    HW = 6400; }
    else if (a4 < 8000) { p = p1; W = 40; stride = 16; lb = 6400; HW = 1600; }
    else                { p = p2; W = 20; stride = 32; lb = 8000; HW = 400;  }
    int hw = a4 - lb;
    int HW4 = HW >> 2;
    const float4* base = (const float4*)(p + (size_t)b * CHN * HW) + (hw >> 2);

    float4 dd[4];
    #pragma unroll
    for (int k = 0; k < 4; k++) {
        float4 v[RB];
        #pragma unroll
        for (int r = 0; r < RB; r++) v[r] = base[(size_t)(k * RB + r) * HW4];
        float4 mx = make_float4(-1e30f, -1e30f, -1e30f, -1e30f);
        #pragma unroll
        for (int r = 0; r < RB; r++) {
            mx.x = fmaxf(mx.x, v[r].x); mx.y = fmaxf(mx.y, v[r].y);
            mx.z = fmaxf(mx.z, v[r].z); mx.w = fmaxf(mx.w, v[r].w);
        }
        float4 s = make_float4(0.f, 0.f, 0.f, 0.f);
        float4 ws = make_float4(0.f, 0.f, 0.f, 0.f);
        #pragma unroll
        for (int r = 0; r < RB; r++) {
            float fr = (float)r;
            float ex = expf(v[r].x - mx.x); s.x += ex; ws.x += ex * fr;
            float ey = expf(v[r].y - mx.y); s.y += ey; ws.y += ey * fr;
            float ez = expf(v[r].z - mx.z); s.z += ez; ws.z += ez * fr;
            float ew = expf(v[r].w - mx.w); s.w += ew; ws.w += ew * fr;
        }
        float st = (float)stride;
        dd[k].x = ws.x / s.x * st; dd[k].y = ws.y / s.y * st;
        dd[k].z = ws.z / s.z * st; dd[k].w = ws.w / s.w * st;
    }

    float4 mx2 = base[(size_t)64 * HW4];
    int lab[4] = {0, 0, 0, 0};
    #pragma unroll 8
    for (int c = 1; c < NC; c++) {
        float4 z = base[(size_t)(64 + c) * HW4];
        if (z.x > mx2.x) { mx2.x = z.x; lab[0] = c; }
        if (z.y > mx2.y) { mx2.y = z.y; lab[1] = c; }
        if (z.z > mx2.z) { mx2.z = z.z; lab[2] = c; }
        if (z.w > mx2.w) { mx2.w = z.w; lab[3] = c; }
    }

    int himg = read_dim(pH), wimg = read_dim(pW);
    float hiW = (float)(wimg - 1), hiH = (float)(himg - 1);
    float st = (float)stride;
    int y0 = hw / W, x0 = hw % W;
    float cy = ((float)y0 + 0.5f) * st;

    #pragma unroll
    for (int j = 0; j < 4; j++) {
        float dl = f4c(dd[0], j), dt = f4c(dd[1], j);
        float dr = f4c(dd[2], j), db = f4c(dd[3], j);
        float mxc = f4c(mx2, j);
        int   lbl = lab[j];
        float cx = ((float)(x0 + j) + 0.5f) * st;
        float x1 = fminf(fmaxf(cx - dl, 0.f), hiW);
        float y1 = fminf(fmaxf(cy - dt, 0.f), hiH);
        float x2 = fminf(fmaxf(cx + dr, 0.f), hiW);
        float y2 = fminf(fmaxf(cy + db, 0.f), hiH);
        int g = b * NA + a4 + j;
        g_boxes[g] = make_float4(x1, y1, x2, y2);
        float sc = 1.0f / (1.0f + expf(-mxc));
        float sp = (sc > CONF) ? sc : -1.0f;
        unsigned u = __float_as_uint(sp);
        u = (u & 0x80000000u) ? ~u : (u | 0x80000000u);
        unsigned hi = ~u;                 // MSB clear <=> score passed conf
        g_keys[g] = ((unsigned long long)hi << 32)
                  | (unsigned)(((a4 + j) << 7) | lbl);
    }
}

// ---------------- Phase B smem (dynamic) ------------------
struct SmemT {
    unsigned long long gath[KP];
    unsigned long long kkey[KP];
    unsigned long long mini[64];
    unsigned long long warr[MAXDET];
    unsigned long long s_thr;
    unsigned int hist[2048];
    float4 sbox[KP];
    short  kidx[KP];
    short  widx[MAXDET];
    short  mem[NC][64];
    unsigned char skeep[KP];
    int ccnt[NC];
    int srank[MAXDET];
    int wsum[33];
    unsigned int wtot[32];
    int s_b, s_rank, s_cnt, s_gcnt, s_mcnt;
};

__device__ __forceinline__ void hist_scan_resolve(SmemT& S, int tid, int w, int lane,
                                                  unsigned rank_) {
    const unsigned full = 0xFFFFFFFFu;
    unsigned e0 = S.hist[2 * tid], e1 = S.hist[2 * tid + 1];
    unsigned incl = e0 + e1;
    #pragma unroll
    for (int o = 1; o < 32; o <<= 1) {
        unsigned t = __shfl_up_sync(full, incl, o);
        if (lane >= o) incl += t;
    }
    if (lane == 31) S.wtot[w] = incl;
    __syncthreads();
    if (w == 0) {
        unsigned v = S.wtot[lane], iv = v;
        #pragma unroll
        for (int o = 1; o < 32; o <<= 1) {
            unsigned t = __shfl_up_sync(full, iv, o);
            if (lane >= o) iv += t;
        }
        S.wtot[lane] = iv - v;
    }
    __syncthreads();
    unsigned incl1 = S.wtot[w] + incl;
    unsigned incl0 = incl1 - e1;
    unsigned excl0 = incl0 - e0, excl1 = incl1 - e1;
    if (e0 && excl0 < rank_ && rank_ <= incl0) { S.s_b = 2 * tid;     S.s_rank = (int)(rank_ - excl0); S.s_cnt = (int)e0; }
    if (e1 && excl1 < rank_ && rank_ <= incl1) { S.s_b = 2 * tid + 1; S.s_rank = (int)(rank_ - excl1); S.s_cnt = (int)e1; }
    __syncthreads();
}

__global__ __launch_bounds__(1024) void topk_nms_k(float* __restrict__ out) {
    if (blockIdx.x >= NB) return;
    extern __shared__ unsigned char dynraw[];
    SmemT& S = *reinterpret_cast<SmemT*>(dynraw);

    int b = blockIdx.x, tid = threadIdx.x, w = tid >> 5, lane = tid & 31;
    const unsigned full = 0xFFFFFFFFu;
    unsigned lt = (1u << lane) - 1u;
    const unsigned long long* keys = g_keys + (size_t)b * NA;
    const int shifts[6] = {53, 42, 31, 20, 9, 0};

    // ===== 1. radix select; pass 0 uses warp-aggregated atomics (hot buckets:
    // all conf-passing scores share sign+exponent -> ~4 distinct 11-bit buckets,
    // plain ATOMS would serialize ~8400 ops on ~4 banks) =====
    unsigned long long prefix = 0, pmask = 0;
    int rank = KP;
    #pragma unroll 1
    for (int pass = 0; pass < 6; pass++) {
        int sh = shifts[pass];
        unsigned bm = (pass == 5) ? 511u : 2047u;
        S.hist[tid] = 0; S.hist[tid + 1024] = 0;
        __syncthreads();
        if (pass == 0) {
            #pragma unroll 1
            for (int n = 0; n < 9; n++) {            // uniform trip (match_any)
                int i = tid + n * 1024;
                bool valid = (i < NA);
                unsigned bucket = 0xFFFFFFFFu;
                if (valid) bucket = (unsigned)(keys[i] >> sh) & bm;
                unsigned grp = __match_any_sync(full, bucket);
                if (valid && lane == (__ffs(grp) - 1))
                    atomicAdd(&S.hist[bucket], (unsigned)__popc(grp));
            }
        } else {
            for (int i = tid; i < NA; i += 1024) {   // later passes: spread buckets
                unsigned long long k = keys[i];
                if ((k & pmask) == prefix)
                    atomicAdd(&S.hist[(unsigned)(k >> sh) & bm], 1u);
            }
        }
        __syncthreads();
        hist_scan_resolve(S, tid, w, lane, (unsigned)rank);
        prefix |= ((unsigned long long)(unsigned)S.s_b) << sh;
        pmask  |= ((unsigned long long)bm) << sh;
        rank = S.s_rank;
        if (S.s_cnt <= 64) break;
    }
    int bcnt = S.s_cnt, brank = rank;
    int below = KP - brank;

    // ===== 2. gather 1024 candidates (validated r11) =====
    if (tid == 0) { S.s_gcnt = 0; S.s_mcnt = 0; }
    if (tid < NC) S.ccnt[tid] = 0;
    __syncthreads();
    #pragma unroll 1
    for (int n2 = 0; n2 < 9; n2++) {
        int i = tid + n2 * 1024;
        unsigned long long k = 0, masked = ~0ull;
        if (i < NA) { k = keys[i]; masked = k & pmask; }
        bool vlo = (masked < prefix);
        bool vm  = (masked == prefix) && (i < NA);
        unsigned blo = __ballot_sync(full, vlo);
        unsigned bmk = __ballot_sync(full, vm);
        int base = 0, base2 = 0;
        if (lane == 0) {
            if (blo) base  = atomicAdd(&S.s_gcnt, __popc(blo));
            if (bmk) base2 = atomicAdd(&S.s_mcnt, __popc(bmk));
        }
        base  = __shfl_sync(full, base, 0);
        base2 = __shfl_sync(full, base2, 0);
        if (vlo) S.gath[base  + __popc(blo & lt)] = k;
        if (vm)  S.mini[base2 + __popc(bmk & lt)] = k;
    }
    __syncthreads();
    if (tid < bcnt) {
        unsigned long long m = S.mini[tid];
        int r = 0;
        for (int j = 0; j < bcnt; j++) r += (S.mini[j] < m);
        if (r < brank) S.gath[below + r] = m;
    }
    __syncthreads();

    // ===== 3+4a. stage (1 LDG; score/label from key) + member lists, fused =====
    unsigned long long mykey = S.gath[tid];
    unsigned klo = (unsigned)(mykey & 0xFFFFFFFFu);
    unsigned khi = (unsigned)(mykey >> 32);
    int myc = (int)(klo & 127u);
    bool act = ((int)khi >= 0);                  // MSB clear <=> conf-passing
    S.sbox[tid] = g_boxes[b * NA + (int)(klo >> 7)];
    S.skeep[tid] = 0;
    int mypos = -1;
    if (act) {
        mypos = atomicAdd(&S.ccnt[myc], 1);
        if (mypos < 64) S.mem[myc][mypos] = (short)tid;
    }
    __syncthreads();

    // ===== 4b. exact in-class key rank -> sorted member lists (validated r11) =====
    int myrank = -1;
    if (act && mypos < 64) {
        int cnt = min(S.ccnt[myc], 64);
        int r = 0;
        for (int j = 0; j < cnt; j++) {
            unsigned long long kj = S.gath[S.mem[myc][j]];
            r += (kj < mykey);
        }
        myrank = r;
    }
    __syncthreads();
    if (myrank >= 0) S.mem[myc][myrank] = (short)tid;
    __syncthreads();

    // ===== 4c. NMS: adjacency-bitmask chains (validated r11) =====
    for (int c = w; c < NC; c += 32) {
        int cnt = min(S.ccnt[c], 64);
        if (cnt == 0) continue;
        const short* mem = S.mem[c];
        float off = (float)c * 4096.0f;

        if (cnt <= 32) {
            int mi = (lane < cnt) ? mem[lane] : -1;
            float4 bb = make_float4(0.f, 0.f, 0.f, 0.f);
            float ar = 0.f;
            if (mi >= 0) {
                float4 t = S.sbox[mi];
                bb = make_float4(__fadd_rn(t.x, off), __fadd_rn(t.y, off),
                                 __fadd_rn(t.z, off), __fadd_rn(t.w, off));
                ar = __fmul_rn(__fsub_rn(bb.z, bb.x), __fsub_rn(bb.w, bb.y));
            }
            unsigned adj = 0;
            #pragma unroll 4
            for (int j = 0; j < cnt; j++) {
                float bx = __shfl_sync(full, bb.x, j);
                float by = __shfl_sync(full, bb.y, j);
                float bz = __shfl_sync(full, bb.z, j);
                float bw = __shfl_sync(full, bb.w, j);
                float aj = __shfl_sync(full, ar, j);
                if (j < lane && mi >= 0) {
                    float lx = fmaxf(bb.x, bx), ly = fmaxf(bb.y, by);
                    float rx = fminf(bb.z, bz), ry = fminf(bb.w, bw);
                    float iw = fmaxf(__fsub_rn(rx, lx), 0.f);
                    float ih = fmaxf(__fsub_rn(ry, ly), 0.f);
                    float inter = __fmul_rn(iw, ih);
                    float den = __fadd_rn(__fsub_rn(__fadd_rn(aj, ar), inter), 1e-7f);
                    if (__fdiv_rn(inter, den) > IOUT) adj |= 1u << j;
                }
            }
            unsigned km = 0;
            #pragma unroll 4
            for (int i = 0; i < cnt; i++) {
                unsigned a = __shfl_sync(full, adj, i);
                if ((a & km) == 0u) km |= 1u << i;
            }
            if (mi >= 0 && ((km >> lane) & 1u)) S.skeep[mi] = 1;
        } else {
            int m0 = (lane < cnt) ? mem[lane] : -1;
            int m1 = (lane + 32 < cnt) ? mem[lane + 32] : -1;
            float4 b0 = make_float4(0.f, 0.f, 0.f, 0.f), b1 = b0;
            float ar0 = 0.f, ar1 = 0.f;
            if (m0 >= 0) {
                float4 t = S.sbox[m0];
                b0 = make_float4(__fadd_rn(t.x, off), __fadd_rn(t.y, off),
                                 __fadd_rn(t.z, off), __fadd_rn(t.w, off));
                ar0 = __fmul_rn(__fsub_rn(b0.z, b0.x), __fsub_rn(b0.w, b0.y));
            }
            if (m1 >= 0) {
                float4 t = S.sbox[m1];
                b1 = make_float4(__fadd_rn(t.x, off), __fadd_rn(t.y, off),
                                 __fadd_rn(t.z, off), __fadd_rn(t.w, off));
                ar1 = __fmul_rn(__fsub_rn(b1.z, b1.x), __fsub_rn(b1.w, b1.y));
            }
            bool sup0 = false, sup1 = false;
            #pragma unroll 1
            for (int i = 0; i < cnt; i++) {
                int d = i >> 5, l = i & 31;
                unsigned sb = __ballot_sync(full, d ? sup1 : sup0);
                bool keep_i = ((sb >> l) & 1u) == 0u;
                if (keep_i) {
                    float bcx = __shfl_sync(full, d ? b1.x : b0.x, l);
                    float bcy = __shfl_sync(full, d ? b1.y : b0.y, l);
                    float bcz = __shfl_sync(full, d ? b1.z : b0.z, l);
                    float bcw = __shfl_sync(full, d ? b1.w : b0.w, l);
                    float ac  = __shfl_sync(full, d ? ar1 : ar0, l);
                    if (m0 >= 0) {
                        float lx = fmaxf(bcx, b0.x), ly = fmaxf(bcy, b0.y);
                        float rx = fminf(bcz, b0.z), ry = fminf(bcw, b0.w);
                        float iw = fmaxf(__fsub_rn(rx, lx), 0.f);
                        float ih = fmaxf(__fsub_rn(ry, ly), 0.f);
                        float inter = __fmul_rn(iw, ih);
                        float den = __fadd_rn(__fsub_rn(__fadd_rn(ac, ar0), inter), 1e-7f);
                        if (__fdiv_rn(inter, den) > IOUT) sup0 = true;
                    }
                    if (m1 >= 0) {
                        float lx = fmaxf(bcx, b1.x), ly = fmaxf(bcy, b1.y);
                        float rx = fminf(bcz, b1.z), ry = fminf(bcw, b1.w);
                        float iw = fmaxf(__fsub_rn(rx, lx), 0.f);
                        float ih = fmaxf(__fsub_rn(ry, ly), 0.f);
                        float inter = __fmul_rn(iw, ih);
                        float den = __fadd_rn(__fsub_rn(__fadd_rn(ac, ar1), inter), 1e-7f);
                        if (__fdiv_rn(inter, den) > IOUT) sup1 = true;
                    }
                    if (lane == l) {
                        if (d) S.skeep[m1] = 1; else S.skeep[m0] = 1;
                    }
                }
            }
        }
    }
    __syncthreads();

    // ===== 5. compact kept candidates =====
    int kv2 = S.skeep[tid];
    unsigned bal2 = __ballot_sync(full, kv2 != 0);
    int wpre = __popc(bal2 & lt);
    if (lane == 0) S.wsum[w] = __popc(bal2);
    __syncthreads();
    if (w == 0) {
        int vv = S.wsum[lane], orig = vv;
        #pragma unroll
        for (int o = 1; o < 32; o <<= 1) {
            int t = __shfl_up_sync(full, vv, o);
            if (lane >= o) vv += t;
        }
        S.wsum[lane] = vv - orig;
        if (lane == 31) S.wsum[32] = vv;
    }
    __syncthreads();
    int n_kept = S.wsum[32];
    if (kv2) {
        int pos = S.wsum[w] + wpre;
        S.kkey[pos] = mykey;
        S.kidx[pos] = (short)tid;
    }
    if (tid == 0) S.s_thr = ~0ull;
    __syncthreads();

    // ===== 6. exact 300th-kept-key threshold (validated r11) =====
    if (n_kept > MAXDET) {
        unsigned long long p2 = 0, m2 = 0;
        int r2 = MAXDET;
        #pragma unroll 1
        for (int pass = 0; pass < 6; pass++) {
            int sh = shifts[pass];
            unsigned bm = (pass == 5) ? 511u : 2047u;
            S.hist[tid] = 0; S.hist[tid + 1024] = 0;
            __syncthreads();
            if (tid < n_kept) {
                unsigned long long k = S.kkey[tid];
                if ((k & m2) == p2)
                    atomicAdd(&S.hist[(unsigned)(k >> sh) & bm], 1u);
            }
            __syncthreads();
            hist_scan_resolve(S, tid, w, lane, (unsigned)r2);
            p2 |= ((unsigned long long)(unsigned)S.s_b) << sh;
            m2 |= ((unsigned long long)bm) << sh;
            r2 = S.s_rank;
            if (S.s_cnt <= 64) break;
        }
        int bc2 = S.s_cnt, br2 = r2;
        if (tid == 0) S.s_mcnt = 0;
        __syncthreads();
        bool vm = (tid < n_kept) && ((S.kkey[tid] & m2) == p2);
        unsigned bmk = __ballot_sync(full, vm);
        int base2 = 0;
        if (lane == 0 && bmk) base2 = atomicAdd(&S.s_mcnt, __popc(bmk));
        base2 = __shfl_sync(full, base2, 0);
        if (vm) S.mini[base2 + __popc(bmk & lt)] = S.kkey[tid];
        __syncthreads();
        if (tid < bc2) {
            unsigned long long m = S.mini[tid];
            int r = 0;
            for (int j = 0; j < bc2; j++) r += (S.mini[j] < m);
            if (r == br2 - 1) S.s_thr = m;
        }
    }
    __syncthreads();
    unsigned long long thr = S.s_thr;

    // ===== 7. compact winners (validated r11) =====
    bool wf = (tid < n_kept) && (S.kkey[tid] <= thr);
    unsigned bw = __ballot_sync(full, wf);
    int wp = __popc(bw & lt);
    if (lane == 0) S.wsum[w] = __popc(bw);
    __syncthreads();
    if (w == 0) {
        int vv = S.wsum[lane], orig = vv;
        #pragma unroll
        for (int o = 1; o < 32; o <<= 1) {
            int t = __shfl_up_sync(full, vv, o);
            if (lane >= o) vv += t;
        }
        S.wsum[lane] = vv - orig;
        if (lane == 31) S.wsum[32] = vv;
    }
    __syncthreads();
    if (wf) {
        int p3 = S.wsum[w] + wp;
        S.warr[p3] = S.kkey[tid];
        S.widx[p3] = S.kidx[tid];
    }
    if (tid < MAXDET) S.srank[tid] = 0;
    __syncthreads();
    int nw = S.wsum[32];

    // ===== 8. exact rank among winners (3 threads/winner) + output =====
    const int OB = 0;
    const int OS = NB * MAXDET * 4;
    const int OL = OS + NB * MAXDET;
    const int OV = OL + NB * MAXDET;

    if (tid < 3 * nw) {
        int i = tid / 3, seg = tid - 3 * i;
        unsigned long long myk = S.warr[i];
        int jb = (seg * nw) / 3, je = ((seg + 1) * nw) / 3;
        int r = 0;
        #pragma unroll 8
        for (int j = jb; j < je; j++) r += (S.warr[j] < myk);
        if (r) atomicAdd(&S.srank[i], r);
    }
    __syncthreads();
    if (tid < nw) {
        int r = S.srank[tid];
        int cand = S.widx[tid];
        unsigned long long wk = S.gath[cand];
        unsigned lo2 = (unsigned)(wk & 0xFFFFFFFFu);
        unsigned hi2 = (unsigned)(wk >> 32);
        unsigned uu = ~hi2;
        unsigned sbits = (uu & 0x80000000u) ? (uu & 0x7FFFFFFFu) : ~uu;
        float4 bx = S.sbox[cand];
        float* ob = out + OB + ((size_t)b * MAXDET + r) * 4;
        ob[0] = bx.x; ob[1] = bx.y; ob[2] = bx.z; ob[3] = bx.w;
        out[OS + b * MAXDET + r] = __uint_as_float(sbits);
        out[OL + b * MAXDET + r] = (float)(lo2 & 127u);
    }
    if (tid < MAXDET) {
        if (tid >= nw) {
            float* ob = out + OB + ((size_t)b * MAXDET + tid) * 4;
            ob[0] = 0.f; ob[1] = 0.f; ob[2] = 0.f; ob[3] = 0.f;
            out[OS + b * MAXDET + tid] = 0.f;
            out[OL + b * MAXDET + tid] = -1.f;
        }
        out[OV + b * MAXDET + tid] = (tid < nw) ? 1.f : 0.f;
    }
}

// ---------------- launch ----------------
extern "C" void kernel_launch(void* const* d_in, const int* in_sizes, int n_in,
                              void* d_out, int out_size) {
    (void)in_sizes; (void)out_size;
    const float* p0 = (const float*)d_in[0];
    const float* p1 = (const float*)d_in[1];
    const float* p2 = (const float*)d_in[2];
    const int* pH = (n_in > 3) ? (const int*)d_in[3] : nullptr;
    const int* pW = (n_in > 4) ? (const int*)d_in[4] : nullptr;

    cudaFuncSetAttribute(topk_nms_k, cudaFuncAttributeMaxDynamicSharedMemorySize,
                         (int)sizeof(SmemT));
    int tot = NB * NA / 4;
    decode_k<<<(tot + 127) / 128, 128>>>(p0, p1, p2, pH, pW);
    topk_nms_k<<<GRID_PAD, 1024, sizeof(SmemT)>>>((float*)d_out);
}

// round 14
// speedup vs baseline: 1.1532x; 1.1319x over previous
#include <cuda_runtime.h>
#include <cstdint>

#define RB 16
#define NC 80
#define NB 16
#define NA 8400
#define CHN 144
#define KP 1024
#define MAXDET 300
#define CONF 0.25f
#define IOUT 0.45f
#define GRID_PAD 160

// ---------------- scratch (no allocations allowed) ----------------
__device__ float4 g_boxes[NB * NA];
__device__ unsigned long long g_keys[NB * NA];

__device__ __forceinline__ int read_dim(const int* p) {
    if (!p) return 640;
    int v = *p;
    if (v > 0 && v < 100000) return v;
    float f = __int_as_float(v);
    return (int)f;
}

__device__ __forceinline__ float f4c(const float4& f, int j) {
    return (j == 0) ? f.x : (j == 1) ? f.y : (j == 2) ? f.z : f.w;
}

// ---------------- Phase A: decode (validated r11 form; at HBM roofline) -----------
__global__ __launch_bounds__(128) void decode_k(const float* __restrict__ p0,
                                                const float* __restrict__ p1,
                                                const float* __restrict__ p2,
                                                const int* pH, const int* pW) {
    int gid = blockIdx.x * blockDim.x + threadIdx.x;
    const int tot = NB * NA / 4;
    if (gid >= tot) return;
    int b = gid / (NA / 4);
    int a4 = (gid - b * (NA / 4)) * 4;

    const float* p; int W, stride, lb, HW;
    if (a4 < 6400)      { p = p0; W = 80; stride = 8;  lb = 0;    HW = 6400; }
    else if (a4 < 8000) { p = p1; W = 40; stride = 16; lb = 6400; HW = 1600; }
    else                { p = p2; W = 20; stride = 32; lb = 8000; HW = 400;  }
    int hw = a4 - lb;
    int HW4 = HW >> 2;
    const float4* base = (const float4*)(p + (size_t)b * CHN * HW) + (hw >> 2);

    float4 dd[4];
    #pragma unroll
    for (int k = 0; k < 4; k++) {
        float4 v[RB];
        #pragma unroll
        for (int r = 0; r < RB; r++) v[r] = base[(size_t)(k * RB + r) * HW4];
        float4 mx = make_float4(-1e30f, -1e30f, -1e30f, -1e30f);
        #pragma unroll
        for (int r = 0; r < RB; r++) {
            mx.x = fmaxf(mx.x, v[r].x); mx.y = fmaxf(mx.y, v[r].y);
            mx.z = fmaxf(mx.z, v[r].z); mx.w = fmaxf(mx.w, v[r].w);
        }
        float4 s = make_float4(0.f, 0.f, 0.f, 0.f);
        float4 ws = make_float4(0.f, 0.f, 0.f, 0.f);
        #pragma unroll
        for (int r = 0; r < RB; r++) {
            float fr = (float)r;
            float ex = expf(v[r].x - mx.x); s.x += ex; ws.x += ex * fr;
            float ey = expf(v[r].y - mx.y); s.y += ey; ws.y += ey * fr;
            float ez = expf(v[r].z - mx.z); s.z += ez; ws.z += ez * fr;
            float ew = expf(v[r].w - mx.w); s.w += ew; ws.w += ew * fr;
        }
        float st = (float)stride;
        dd[k].x = ws.x / s.x * st; dd[k].y = ws.y / s.y * st;
        dd[k].z = ws.z / s.z * st; dd[k].w = ws.w / s.w * st;
    }

    float4 mx2 = base[(size_t)64 * HW4];
    int lab[4] = {0, 0, 0, 0};
    #pragma unroll 8
    for (int c = 1; c < NC; c++) {
        float4 z = base[(size_t)(64 + c) * HW4];
        if (z.x > mx2.x) { mx2.x = z.x; lab[0] = c; }
        if (z.y > mx2.y) { mx2.y = z.y; lab[1] = c; }
        if (z.z > mx2.z) { mx2.z = z.z; lab[2] = c; }
        if (z.w > mx2.w) { mx2.w = z.w; lab[3] = c; }
    }

    int himg = read_dim(pH), wimg = read_dim(pW);
    float hiW = (float)(wimg - 1), hiH = (float)(himg - 1);
    float st = (float)stride;
    int y0 = hw / W, x0 = hw % W;
    float cy = ((float)y0 + 0.5f) * st;

    #pragma unroll
    for (int j = 0; j < 4; j++) {
        float dl = f4c(dd[0], j), dt = f4c(dd[1], j);
        float dr = f4c(dd[2], j), db = f4c(dd[3], j);
        float mxc = f4c(mx2, j);
        int   lbl = lab[j];
        float cx = ((float)(x0 + j) + 0.5f) * st;
        float x1 = fminf(fmaxf(cx - dl, 0.f), hiW);
        float y1 = fminf(fmaxf(cy - dt, 0.f), hiH);
        float x2 = fminf(fmaxf(cx + dr, 0.f), hiW);
        float y2 = fminf(fmaxf(cy + db, 0.f), hiH);
        int g = b * NA + a4 + j;
        g_boxes[g] = make_float4(x1, y1, x2, y2);
        float sc = 1.0f / (1.0f + expf(-mxc));
        float sp = (sc > CONF) ? sc : -1.0f;
        unsigned u = __float_as_uint(sp);
        u = (u & 0x80000000u) ? ~u : (u | 0x80000000u);
        unsigned hi = ~u;                 // MSB clear <=> score passed conf
        g_keys[g] = ((unsigned long long)hi << 32)
                  | (unsigned)(((a4 + j) << 7) | lbl);
    }
}

// ---------------- Phase B smem (dynamic) ------------------
struct SmemT {
    unsigned long long gath[KP];
    unsigned long long kkey[KP];
    unsigned long long sorted[KP];
    unsigned long long mini[64];
    unsigned long long s_thr;
    unsigned int hist[2048];
    int cur[2048];
    float4 sbox[KP];
    short  kidx[KP];
    short  mem[NC][64];
    unsigned char skeep[KP];
    int ccnt[NC];
    int wsum[33];
    unsigned int wtot[32];
    int s_b, s_rank, s_cnt, s_gcnt, s_mcnt;
};

__device__ __forceinline__ void hist_scan_resolve(SmemT& S, int tid, int w, int lane,
                                                  unsigned rank_) {
    const unsigned full = 0xFFFFFFFFu;
    unsigned e0 = S.hist[2 * tid], e1 = S.hist[2 * tid + 1];
    unsigned incl = e0 + e1;
    #pragma unroll
    for (int o = 1; o < 32; o <<= 1) {
        unsigned t = __shfl_up_sync(full, incl, o);
        if (lane >= o) incl += t;
    }
    if (lane == 31) S.wtot[w] = incl;
    __syncthreads();
    if (w == 0) {
        unsigned v = S.wtot[lane], iv = v;
        #pragma unroll
        for (int o = 1; o < 32; o <<= 1) {
            unsigned t = __shfl_up_sync(full, iv, o);
            if (lane >= o) iv += t;
        }
        S.wtot[lane] = iv - v;
    }
    __syncthreads();
    unsigned incl1 = S.wtot[w] + incl;
    unsigned incl0 = incl1 - e1;
    unsigned excl0 = incl0 - e0, excl1 = incl1 - e1;
    if (e0 && excl0 < rank_ && rank_ <= incl0) { S.s_b = 2 * tid;     S.s_rank = (int)(rank_ - excl0); S.s_cnt = (int)e0; }
    if (e1 && excl1 < rank_ && rank_ <= incl1) { S.s_b = 2 * tid + 1; S.s_rank = (int)(rank_ - excl1); S.s_cnt = (int)e1; }
    __syncthreads();
}

__global__ __launch_bounds__(1024) void topk_nms_k(float* __restrict__ out) {
    if (blockIdx.x >= NB) return;
    extern __shared__ unsigned char dynraw[];
    SmemT& S = *reinterpret_cast<SmemT*>(dynraw);

    int b = blockIdx.x, tid = threadIdx.x, w = tid >> 5, lane = tid & 31;
    const unsigned full = 0xFFFFFFFFu;
    unsigned lt = (1u << lane) - 1u;
    const unsigned long long* keys = g_keys + (size_t)b * NA;
    const int shifts[6] = {53, 42, 31, 20, 9, 0};

    // ===== 1. radix select (byte-identical r11) =====
    unsigned long long prefix = 0, pmask = 0;
    int rank = KP;
    #pragma unroll 1
    for (int pass = 0; pass < 6; pass++) {
        int sh = shifts[pass];
        unsigned bm = (pass == 5) ? 511u : 2047u;
        S.hist[tid] = 0; S.hist[tid + 1024] = 0;
        __syncthreads();
        for (int i = tid; i < NA; i += 1024) {
            unsigned long long k = keys[i];
            if ((k & pmask) == prefix)
                atomicAdd(&S.hist[(unsigned)(k >> sh) & bm], 1u);
        }
        __syncthreads();
        hist_scan_resolve(S, tid, w, lane, (unsigned)rank);
        prefix |= ((unsigned long long)(unsigned)S.s_b) << sh;
        pmask  |= ((unsigned long long)bm) << sh;
        rank = S.s_rank;
        if (S.s_cnt <= 64) break;
    }
    int bcnt = S.s_cnt, brank = rank;
    int below = KP - brank;

    // ===== 2. gather 1024 candidates (byte-identical r11) =====
    if (tid == 0) { S.s_gcnt = 0; S.s_mcnt = 0; }
    if (tid < NC) S.ccnt[tid] = 0;
    __syncthreads();
    #pragma unroll 1
    for (int n2 = 0; n2 < 9; n2++) {
        int i = tid + n2 * 1024;
        unsigned long long k = 0, masked = ~0ull;
        if (i < NA) { k = keys[i]; masked = k & pmask; }
        bool vlo = (masked < prefix);
        bool vm  = (masked == prefix) && (i < NA);
        unsigned blo = __ballot_sync(full, vlo);
        unsigned bmk = __ballot_sync(full, vm);
        int base = 0, base2 = 0;
        if (lane == 0) {
            if (blo) base  = atomicAdd(&S.s_gcnt, __popc(blo));
            if (bmk) base2 = atomicAdd(&S.s_mcnt, __popc(bmk));
        }
        base  = __shfl_sync(full, base, 0);
        base2 = __shfl_sync(full, base2, 0);
        if (vlo) S.gath[base  + __popc(blo & lt)] = k;
        if (vm)  S.mini[base2 + __popc(bmk & lt)] = k;
    }
    __syncthreads();
    if (tid < bcnt) {
        unsigned long long m = S.mini[tid];
        int r = 0;
        for (int j = 0; j < bcnt; j++) r += (S.mini[j] < m);
        if (r < brank) S.gath[below + r] = m;
    }
    __syncthreads();

    // ===== 3+4a. stage + member lists (byte-identical r11) =====
    unsigned long long mykey = S.gath[tid];
    unsigned klo = (unsigned)(mykey & 0xFFFFFFFFu);
    unsigned khi = (unsigned)(mykey >> 32);
    int myc = (int)(klo & 127u);
    bool act = ((int)khi >= 0);                  // MSB clear <=> conf-passing
    S.sbox[tid] = g_boxes[b * NA + (int)(klo >> 7)];
    S.skeep[tid] = 0;
    int mypos = -1;
    if (act) {
        mypos = atomicAdd(&S.ccnt[myc], 1);
        if (mypos < 64) S.mem[myc][mypos] = (short)tid;
    }
    __syncthreads();

    // ===== 4b. exact in-class key rank -> sorted member lists (r11) =====
    int myrank = -1;
    if (act && mypos < 64) {
        int cnt = min(S.ccnt[myc], 64);
        int r = 0;
        for (int j = 0; j < cnt; j++) {
            unsigned long long kj = S.gath[S.mem[myc][j]];
            r += (kj < mykey);
        }
        myrank = r;
    }
    __syncthreads();
    if (myrank >= 0) S.mem[myc][myrank] = (short)tid;
    __syncthreads();

    // ===== 4c. NMS: adjacency-bitmask chains (byte-identical r11) =====
    for (int c = w; c < NC; c += 32) {
        int cnt = min(S.ccnt[c], 64);
        if (cnt == 0) continue;
        const short* mem = S.mem[c];
        float off = (float)c * 4096.0f;

        if (cnt <= 32) {
            int mi = (lane < cnt) ? mem[lane] : -1;
            float4 bb = make_float4(0.f, 0.f, 0.f, 0.f);
            float ar = 0.f;
            if (mi >= 0) {
                float4 t = S.sbox[mi];
                bb = make_float4(__fadd_rn(t.x, off), __fadd_rn(t.y, off),
                                 __fadd_rn(t.z, off), __fadd_rn(t.w, off));
                ar = __fmul_rn(__fsub_rn(bb.z, bb.x), __fsub_rn(bb.w, bb.y));
            }
            unsigned adj = 0;
            #pragma unroll 4
            for (int j = 0; j < cnt; j++) {
                float bx = __shfl_sync(full, bb.x, j);
                float by = __shfl_sync(full, bb.y, j);
                float bz = __shfl_sync(full, bb.z, j);
                float bw = __shfl_sync(full, bb.w, j);
                float aj = __shfl_sync(full, ar, j);
                if (j < lane && mi >= 0) {
                    float lx = fmaxf(bb.x, bx), ly = fmaxf(bb.y, by);
                    float rx = fminf(bb.z, bz), ry = fminf(bb.w, bw);
                    float iw = fmaxf(__fsub_rn(rx, lx), 0.f);
                    float ih = fmaxf(__fsub_rn(ry, ly), 0.f);
                    float inter = __fmul_rn(iw, ih);
                    float den = __fadd_rn(__fsub_rn(__fadd_rn(aj, ar), inter), 1e-7f);
                    if (__fdiv_rn(inter, den) > IOUT) adj |= 1u << j;
                }
            }
            unsigned km = 0;
            #pragma unroll 4
            for (int i = 0; i < cnt; i++) {
                unsigned a = __shfl_sync(full, adj, i);
                if ((a & km) == 0u) km |= 1u << i;
            }
            if (mi >= 0 && ((km >> lane) & 1u)) S.skeep[mi] = 1;
        } else {
            int m0 = (lane < cnt) ? mem[lane] : -1;
            int m1 = (lane + 32 < cnt) ? mem[lane + 32] : -1;
            float4 b0 = make_float4(0.f, 0.f, 0.f, 0.f), b1 = b0;
            float ar0 = 0.f, ar1 = 0.f;
            if (m0 >= 0) {
                float4 t = S.sbox[m0];
                b0 = make_float4(__fadd_rn(t.x, off), __fadd_rn(t.y, off),
                                 __fadd_rn(t.z, off), __fadd_rn(t.w, off));
                ar0 = __fmul_rn(__fsub_rn(b0.z, b0.x), __fsub_rn(b0.w, b0.y));
            }
            if (m1 >= 0) {
                float4 t = S.sbox[m1];
                b1 = make_float4(__fadd_rn(t.x, off), __fadd_rn(t.y, off),
                                 __fadd_rn(t.z, off), __fadd_rn(t.w, off));
                ar1 = __fmul_rn(__fsub_rn(b1.z, b1.x), __fsub_rn(b1.w, b1.y));
            }
            bool sup0 = false, sup1 = false;
            #pragma unroll 1
            for (int i = 0; i < cnt; i++) {
                int d = i >> 5, l = i & 31;
                unsigned sb = __ballot_sync(full, d ? sup1 : sup0);
                bool keep_i = ((sb >> l) & 1u) == 0u;
                if (keep_i) {
                    float bcx = __shfl_sync(full, d ? b1.x : b0.x, l);
                    float bcy = __shfl_sync(full, d ? b1.y : b0.y, l);
                    float bcz = __shfl_sync(full, d ? b1.z : b0.z, l);
                    float bcw = __shfl_sync(full, d ? b1.w : b0.w, l);
                    float ac  = __shfl_sync(full, d ? ar1 : ar0, l);
                    if (m0 >= 0) {
                        float lx = fmaxf(bcx, b0.x), ly = fmaxf(bcy, b0.y);
                        float rx = fminf(bcz, b0.z), ry = fminf(bcw, b0.w);
                        float iw = fmaxf(__fsub_rn(rx, lx), 0.f);
                        float ih = fmaxf(__fsub_rn(ry, ly), 0.f);
                        float inter = __fmul_rn(iw, ih);
                        float den = __fadd_rn(__fsub_rn(__fadd_rn(ac, ar0), inter), 1e-7f);
                        if (__fdiv_rn(inter, den) > IOUT) sup0 = true;
                    }
                    if (m1 >= 0) {
                        float lx = fmaxf(bcx, b1.x), ly = fmaxf(bcy, b1.y);
                        float rx = fminf(bcz, b1.z), ry = fminf(bcw, b1.w);
                        float iw = fmaxf(__fsub_rn(rx, lx), 0.f);
                        float ih = fmaxf(__fsub_rn(ry, ly), 0.f);
                        float inter = __fmul_rn(iw, ih);
                        float den = __fadd_rn(__fsub_rn(__fadd_rn(ac, ar1), inter), 1e-7f);
                        if (__fdiv_rn(inter, den) > IOUT) sup1 = true;
                    }
                    if (lane == l) {
                        if (d) S.skeep[m1] = 1; else S.skeep[m0] = 1;
                    }
                }
            }
        }
    }
    __syncthreads();

    // ===== 5. compact kept candidates (byte-identical r11) =====
    int kv2 = S.skeep[tid];
    unsigned bal2 = __ballot_sync(full, kv2 != 0);
    int wpre = __popc(bal2 & lt);
    if (lane == 0) S.wsum[w] = __popc(bal2);
    __syncthreads();
    if (w == 0) {
        int vv = S.wsum[lane], orig = vv;
        #pragma unroll
        for (int o = 1; o < 32; o <<= 1) {
            int t = __shfl_up_sync(full, vv, o);
            if (lane >= o) vv += t;
        }
        S.wsum[lane] = vv - orig;
        if (lane == 31) S.wsum[32] = vv;
    }
    __syncthreads();
    int n_kept = S.wsum[32];
    if (kv2) {
        int pos = S.wsum[w] + wpre;
        S.kkey[pos] = mykey;
        S.kidx[pos] = (short)tid;
    }
    __syncthreads();

    // ===== 6'. exact ranks among ALL kept via monotone bucket-rank =====
    // (replaces r11 phases 6+7+8: winners are rank<MAXDET, slot=rank — identical)
    unsigned long long kq = (tid < n_kept) ? S.kkey[tid] : ~0ull;
    unsigned long long kxv = (tid < n_kept) ? S.kkey[tid] : 0ull;
    #pragma unroll
    for (int o = 16; o > 0; o >>= 1) {
        unsigned long long t1 = __shfl_xor_sync(full, kq, o);
        unsigned long long t2 = __shfl_xor_sync(full, kxv, o);
        kq = (t1 < kq) ? t1 : kq;
        kxv = (t2 > kxv) ? t2 : kxv;
    }
    if (lane == 0) { S.mini[w] = kq; S.mini[32 + w] = kxv; }
    __syncthreads();
    if (w == 0) {
        unsigned long long a = S.mini[lane], b2 = S.mini[32 + lane];
        #pragma unroll
        for (int o = 16; o > 0; o >>= 1) {
            unsigned long long t1 = __shfl_xor_sync(full, a, o);
            unsigned long long t2 = __shfl_xor_sync(full, b2, o);
            a = (t1 < a) ? t1 : a;
            b2 = (t2 > b2) ? t2 : b2;
        }
        if (lane == 0) {
            S.s_thr = a;
            unsigned long long range = b2 - a;
            int hb = 63 - __clzll(range | 1ull);
            S.s_b = (hb > 10) ? (hb - 10) : 0;     // (range>>shift) < 2048
        }
    }
    S.hist[tid] = 0; S.hist[tid + 1024] = 0;
    __syncthreads();
    unsigned long long kmin = S.s_thr;
    int bshift = S.s_b;
    int myb = -1;
    if (tid < n_kept) {
        myb = (int)((S.kkey[tid] - kmin) >> bshift);
        atomicAdd(&S.hist[myb], 1u);               // ~1000 atomics, spread buckets
    }
    __syncthreads();
    // exclusive scan over 2048 buckets -> S.cur (counts stay in S.hist)
    {
        unsigned e0 = S.hist[2 * tid], e1 = S.hist[2 * tid + 1];
        unsigned incl = e0 + e1;
        #pragma unroll
        for (int o = 1; o < 32; o <<= 1) {
            unsigned t = __shfl_up_sync(full, incl, o);
            if (lane >= o) incl += t;
        }
        if (lane == 31) S.wtot[w] = incl;
        __syncthreads();
        if (w == 0) {
            unsigned v = S.wtot[lane], iv = v;
            #pragma unroll
            for (int o = 1; o < 32; o <<= 1) {
                unsigned t = __shfl_up_sync(full, iv, o);
                if (lane >= o) iv += t;
            }
            S.wtot[lane] = iv - v;
        }
        __syncthreads();
        unsigned incl1 = S.wtot[w] + incl;
        unsigned excl0 = incl1 - e1 - e0;
        S.cur[2 * tid] = (int)excl0;
        S.cur[2 * tid + 1] = (int)(excl0 + e0);
    }
    __syncthreads();
    int myexcl = 0, mycnt = 0;
    if (myb >= 0) { myexcl = S.cur[myb]; mycnt = (int)S.hist[myb]; }
    __syncthreads();
    if (myb >= 0) {
        int p = atomicAdd(&S.cur[myb], 1);
        S.sorted[p] = S.kkey[tid];
    }
    __syncthreads();
    int grank = -1;
    if (myb >= 0) {
        unsigned long long mk = S.kkey[tid];
        int r = myexcl;
        for (int j = myexcl; j < myexcl + mycnt; j++) r += (S.sorted[j] < mk);
        grank = r;                                  // exact global rank among kept
    }

    // ===== 7'. output =====
    const int OB = 0;
    const int OS = NB * MAXDET * 4;
    const int OL = OS + NB * MAXDET;
    const int OV = OL + NB * MAXDET;

    if (grank >= 0 && grank < MAXDET) {
        int cand = S.kidx[tid];
        unsigned long long wk = S.gath[cand];
        unsigned lo2 = (unsigned)(wk & 0xFFFFFFFFu);
        unsigned hi2 = (unsigned)(wk >> 32);
        unsigned uu = ~hi2;
        unsigned sbits = (uu & 0x80000000u) ? (uu & 0x7FFFFFFFu) : ~uu;
        float4 bx = S.sbox[cand];
        float* ob = out + OB + ((size_t)b * MAXDET + grank) * 4;
        ob[0] = bx.x; ob[1] = bx.y; ob[2] = bx.z; ob[3] = bx.w;
        out[OS + b * MAXDET + grank] = __uint_as_float(sbits);
        out[OL + b * MAXDET + grank] = (float)(lo2 & 127u);
    }
    int n = min(n_kept, MAXDET);
    if (tid < MAXDET) {
        if (tid >= n) {
            float* ob = out + OB + ((size_t)b * MAXDET + tid) * 4;
            ob[0] = 0.f; ob[1] = 0.f; ob[2] = 0.f; ob[3] = 0.f;
            out[OS + b * MAXDET + tid] = 0.f;
            out[OL + b * MAXDET + tid] = -1.f;
        }
        out[OV + b * MAXDET + tid] = (tid < n) ? 1.f : 0.f;
    }
}

// ---------------- launch ----------------
extern "C" void kernel_launch(void* const* d_in, const int* in_sizes, int n_in,
                              void* d_out, int out_size) {
    (void)in_sizes; (void)out_size;
    const float* p0 = (const float*)d_in[0];
    const float* p1 = (const float*)d_in[1];
    const float* p2 = (const float*)d_in[2];
    const int* pH = (n_in > 3) ? (const int*)d_in[3] : nullptr;
    const int* pW = (n_in > 4) ? (const int*)d_in[4] : nullptr;

    cudaFuncSetAttribute(topk_nms_k, cudaFuncAttributeMaxDynamicSharedMemorySize,
                         (int)sizeof(SmemT));
    int tot = NB * NA / 4;
    decode_k<<<(tot + 127) / 128, 128>>>(p0, p1, p2, pH, pW);
    topk_nms_k<<<GRID_PAD, 1024, sizeof(SmemT)>>>((float*)d_out);
}

// round 15
// speedup vs baseline: 1.1997x; 1.0403x over previous
#include <cuda_runtime.h>
#include <cstdint>

#define RB 16
#define NC 80
#define NB 16
#define NA 8400
#define CHN 144
#define KP 1024
#define MAXDET 300
#define CONF 0.25f
#define IOUT 0.45f
#define GRID_PAD 160

// ---------------- scratch (no allocations allowed) ----------------
__device__ float4 g_boxes[NB * NA];
__device__ unsigned long long g_keys[NB * NA];

__device__ __forceinline__ int read_dim(const int* p) {
    if (!p) return 640;
    int v = *p;
    if (v > 0 && v < 100000) return v;
    float f = __int_as_float(v);
    return (int)f;
}

__device__ __forceinline__ float f4c(const float4& f, int j) {
    return (j == 0) ? f.x : (j == 1) ? f.y : (j == 2) ? f.z : f.w;
}

// ---------------- Phase A: decode (validated; at HBM roofline) -----------
__global__ __launch_bounds__(128) void decode_k(const float* __restrict__ p0,
                                                const float* __restrict__ p1,
                                                const float* __restrict__ p2,
                                                const int* pH, const int* pW) {
    int gid = blockIdx.x * blockDim.x + threadIdx.x;
    const int tot = NB * NA / 4;
    if (gid >= tot) return;
    int b = gid / (NA / 4);
    int a4 = (gid - b * (NA / 4)) * 4;

    const float* p; int W, stride, lb, HW;
    if (a4 < 6400)      { p = p0; W = 80; stride = 8;  lb = 0;    HW = 6400; }
    else if (a4 < 8000) { p = p1; W = 40; stride = 16; lb = 6400; HW = 1600; }
    else                { p = p2; W = 20; stride = 32; lb = 8000; HW = 400;  }
    int hw = a4 - lb;
    int HW4 = HW >> 2;
    const float4* base = (const float4*)(p + (size_t)b * CHN * HW) + (hw >> 2);

    float4 dd[4];
    #pragma unroll
    for (int k = 0; k < 4; k++) {
        float4 v[RB];
        #pragma unroll
        for (int r = 0; r < RB; r++) v[r] = base[(size_t)(k * RB + r) * HW4];
        float4 mx = make_float4(-1e30f, -1e30f, -1e30f, -1e30f);
        #pragma unroll
        for (int r = 0; r < RB; r++) {
            mx.x = fmaxf(mx.x, v[r].x); mx.y = fmaxf(mx.y, v[r].y);
            mx.z = fmaxf(mx.z, v[r].z); mx.w = fmaxf(mx.w, v[r].w);
        }
        float4 s = make_float4(0.f, 0.f, 0.f, 0.f);
        float4 ws = make_float4(0.f, 0.f, 0.f, 0.f);
        #pragma unroll
        for (int r = 0; r < RB; r++) {
            float fr = (float)r;
            float ex = expf(v[r].x - mx.x); s.x += ex; ws.x += ex * fr;
            float ey = expf(v[r].y - mx.y); s.y += ey; ws.y += ey * fr;
            float ez = expf(v[r].z - mx.z); s.z += ez; ws.z += ez * fr;
            float ew = expf(v[r].w - mx.w); s.w += ew; ws.w += ew * fr;
        }
        float st = (float)stride;
        dd[k].x = ws.x / s.x * st; dd[k].y = ws.y / s.y * st;
        dd[k].z = ws.z / s.z * st; dd[k].w = ws.w / s.w * st;
    }

    float4 mx2 = base[(size_t)64 * HW4];
    int lab[4] = {0, 0, 0, 0};
    #pragma unroll 8
    for (int c = 1; c < NC; c++) {
        float4 z = base[(size_t)(64 + c) * HW4];
        if (z.x > mx2.x) { mx2.x = z.x; lab[0] = c; }
        if (z.y > mx2.y) { mx2.y = z.y; lab[1] = c; }
        if (z.z > mx2.z) { mx2.z = z.z; lab[2] = c; }
        if (z.w > mx2.w) { mx2.w = z.w; lab[3] = c; }
    }

    int himg = read_dim(pH), wimg = read_dim(pW);
    float hiW = (float)(wimg - 1), hiH = (float)(himg - 1);
    float st = (float)stride;
    int y0 = hw / W, x0 = hw % W;
    float cy = ((float)y0 + 0.5f) * st;

    #pragma unroll
    for (int j = 0; j < 4; j++) {
        float dl = f4c(dd[0], j), dt = f4c(dd[1], j);
        float dr = f4c(dd[2], j), db = f4c(dd[3], j);
        float mxc = f4c(mx2, j);
        int   lbl = lab[j];
        float cx = ((float)(x0 + j) + 0.5f) * st;
        float x1 = fminf(fmaxf(cx - dl, 0.f), hiW);
        float y1 = fminf(fmaxf(cy - dt, 0.f), hiH);
        float x2 = fminf(fmaxf(cx + dr, 0.f), hiW);
        float y2 = fminf(fmaxf(cy + db, 0.f), hiH);
        int g = b * NA + a4 + j;
        g_boxes[g] = make_float4(x1, y1, x2, y2);
        float sc = 1.0f / (1.0f + expf(-mxc));
        float sp = (sc > CONF) ? sc : -1.0f;
        unsigned u = __float_as_uint(sp);
        u = (u & 0x80000000u) ? ~u : (u | 0x80000000u);
        unsigned hi = ~u;                 // MSB clear <=> score passed conf
        g_keys[g] = ((unsigned long long)hi << 32)
                  | (unsigned)(((a4 + j) << 7) | lbl);
    }
}

// ---------------- Phase B smem (dynamic) ------------------
struct SmemT {
    unsigned long long gath[KP];
    unsigned long long kkey[KP];
    unsigned long long sorted[KP];
    unsigned long long mini[64];
    unsigned long long s_thr;
    unsigned int hist[2048];
    int cur[2048];
    float4 sbox[KP];
    short  kidx[KP];
    short  mem[NC][64];
    unsigned char skeep[KP];
    int ccnt[NC];
    int wsum[33];
    unsigned int wtot[32];
    int s_b, s_rank, s_cnt, s_gcnt, s_mcnt;
};

// scan 2048-bin hist, find bucket holding rank_; also RE-ZEROES each thread's
// own two bins after reading them (exclusive ownership; barriers below publish),
// so callers never need a separate zeroing step for the next histogram.
__device__ __forceinline__ void hist_scan_resolve(SmemT& S, int tid, int w, int lane,
                                                  unsigned rank_) {
    const unsigned full = 0xFFFFFFFFu;
    unsigned e0 = S.hist[2 * tid], e1 = S.hist[2 * tid + 1];
    S.hist[2 * tid] = 0; S.hist[2 * tid + 1] = 0;
    unsigned incl = e0 + e1;
    #pragma unroll
    for (int o = 1; o < 32; o <<= 1) {
        unsigned t = __shfl_up_sync(full, incl, o);
        if (lane >= o) incl += t;
    }
    if (lane == 31) S.wtot[w] = incl;
    __syncthreads();
    if (w == 0) {
        unsigned v = S.wtot[lane], iv = v;
        #pragma unroll
        for (int o = 1; o < 32; o <<= 1) {
            unsigned t = __shfl_up_sync(full, iv, o);
            if (lane >= o) iv += t;
        }
        S.wtot[lane] = iv - v;
    }
    __syncthreads();
    unsigned incl1 = S.wtot[w] + incl;
    unsigned incl0 = incl1 - e1;
    unsigned excl0 = incl0 - e0, excl1 = incl1 - e1;
    if (e0 && excl0 < rank_ && rank_ <= incl0) { S.s_b = 2 * tid;     S.s_rank = (int)(rank_ - excl0); S.s_cnt = (int)e0; }
    if (e1 && excl1 < rank_ && rank_ <= incl1) { S.s_b = 2 * tid + 1; S.s_rank = (int)(rank_ - excl1); S.s_cnt = (int)e1; }
    __syncthreads();
}

__global__ __launch_bounds__(1024) void topk_nms_k(float* __restrict__ out) {
    if (blockIdx.x >= NB) return;
    extern __shared__ unsigned char dynraw[];
    SmemT& S = *reinterpret_cast<SmemT*>(dynraw);

    int b = blockIdx.x, tid = threadIdx.x, w = tid >> 5, lane = tid & 31;
    const unsigned full = 0xFFFFFFFFu;
    unsigned lt = (1u << lane) - 1u;
    const unsigned long long* keys = g_keys + (size_t)b * NA;
    const int shifts[6] = {53, 42, 31, 20, 9, 0};

    // ===== entry: single zeroing block (hist + all counters) =====
    S.hist[tid] = 0; S.hist[tid + 1024] = 0;
    if (tid == 0) { S.s_gcnt = 0; S.s_mcnt = 0; }
    if (tid < NC) S.ccnt[tid] = 0;
    __syncthreads();

    // ===== 1. radix select (validated; zeroing folded into resolve) =====
    unsigned long long prefix = 0, pmask = 0;
    int rank = KP;
    #pragma unroll 1
    for (int pass = 0; pass < 6; pass++) {
        int sh = shifts[pass];
        unsigned bm = (pass == 5) ? 511u : 2047u;
        for (int i = tid; i < NA; i += 1024) {
            unsigned long long k = keys[i];
            if ((k & pmask) == prefix)
                atomicAdd(&S.hist[(unsigned)(k >> sh) & bm], 1u);
        }
        __syncthreads();
        hist_scan_resolve(S, tid, w, lane, (unsigned)rank);   // also re-zeroes hist
        prefix |= ((unsigned long long)(unsigned)S.s_b) << sh;
        pmask  |= ((unsigned long long)bm) << sh;
        rank = S.s_rank;
        if (S.s_cnt <= 64) break;
    }
    int bcnt = S.s_cnt, brank = rank;
    int below = KP - brank;

    // ===== 2. gather 1024 candidates (validated r11/r14) =====
    #pragma unroll 1
    for (int n2 = 0; n2 < 9; n2++) {
        int i = tid + n2 * 1024;
        unsigned long long k = 0, masked = ~0ull;
        if (i < NA) { k = keys[i]; masked = k & pmask; }
        bool vlo = (masked < prefix);
        bool vm  = (masked == prefix) && (i < NA);
        unsigned blo = __ballot_sync(full, vlo);
        unsigned bmk = __ballot_sync(full, vm);
        int base = 0, base2 = 0;
        if (lane == 0) {
            if (blo) base  = atomicAdd(&S.s_gcnt, __popc(blo));
            if (bmk) base2 = atomicAdd(&S.s_mcnt, __popc(bmk));
        }
        base  = __shfl_sync(full, base, 0);
        base2 = __shfl_sync(full, base2, 0);
        if (vlo) S.gath[base  + __popc(blo & lt)] = k;
        if (vm)  S.mini[base2 + __popc(bmk & lt)] = k;
    }
    __syncthreads();
    if (tid < bcnt) {
        unsigned long long m = S.mini[tid];
        int r = 0;
        for (int j = 0; j < bcnt; j++) r += (S.mini[j] < m);
        if (r < brank) S.gath[below + r] = m;
    }
    __syncthreads();

    // ===== 3+4a. stage + member lists (validated) =====
    unsigned long long mykey = S.gath[tid];
    unsigned klo = (unsigned)(mykey & 0xFFFFFFFFu);
    unsigned khi = (unsigned)(mykey >> 32);
    int myc = (int)(klo & 127u);
    bool act = ((int)khi >= 0);                  // MSB clear <=> conf-passing
    S.sbox[tid] = g_boxes[b * NA + (int)(klo >> 7)];
    S.skeep[tid] = 0;
    int mypos = -1;
    if (act) {
        mypos = atomicAdd(&S.ccnt[myc], 1);
        if (mypos < 64) S.mem[myc][mypos] = (short)tid;
    }
    __syncthreads();

    // ===== 4b. exact in-class key rank -> sorted member lists (validated) =====
    int myrank = -1;
    if (act && mypos < 64) {
        int cnt = min(S.ccnt[myc], 64);
        int r = 0;
        for (int j = 0; j < cnt; j++) {
            unsigned long long kj = S.gath[S.mem[myc][j]];
            r += (kj < mykey);
        }
        myrank = r;
    }
    __syncthreads();
    if (myrank >= 0) S.mem[myc][myrank] = (short)tid;
    __syncthreads();

    // ===== 4c. NMS: adjacency-bitmask chains (validated) =====
    for (int c = w; c < NC; c += 32) {
        int cnt = min(S.ccnt[c], 64);
        if (cnt == 0) continue;
        const short* mem = S.mem[c];
        float off = (float)c * 4096.0f;

        if (cnt <= 32) {
            int mi = (lane < cnt) ? mem[lane] : -1;
            float4 bb = make_float4(0.f, 0.f, 0.f, 0.f);
            float ar = 0.f;
            if (mi >= 0) {
                float4 t = S.sbox[mi];
                bb = make_float4(__fadd_rn(t.x, off), __fadd_rn(t.y, off),
                                 __fadd_rn(t.z, off), __fadd_rn(t.w, off));
                ar = __fmul_rn(__fsub_rn(bb.z, bb.x), __fsub_rn(bb.w, bb.y));
            }
            unsigned adj = 0;
            #pragma unroll 4
            for (int j = 0; j < cnt; j++) {
                float bx = __shfl_sync(full, bb.x, j);
                float by = __shfl_sync(full, bb.y, j);
                float bz = __shfl_sync(full, bb.z, j);
                float bw = __shfl_sync(full, bb.w, j);
                float aj = __shfl_sync(full, ar, j);
                if (j < lane && mi >= 0) {
                    float lx = fmaxf(bb.x, bx), ly = fmaxf(bb.y, by);
                    float rx = fminf(bb.z, bz), ry = fminf(bb.w, bw);
                    float iw = fmaxf(__fsub_rn(rx, lx), 0.f);
                    float ih = fmaxf(__fsub_rn(ry, ly), 0.f);
                    float inter = __fmul_rn(iw, ih);
                    float den = __fadd_rn(__fsub_rn(__fadd_rn(aj, ar), inter), 1e-7f);
                    if (__fdiv_rn(inter, den) > IOUT) adj |= 1u << j;
                }
            }
            unsigned km = 0;
            #pragma unroll 4
            for (int i = 0; i < cnt; i++) {
                unsigned a = __shfl_sync(full, adj, i);
                if ((a & km) == 0u) km |= 1u << i;
            }
            if (mi >= 0 && ((km >> lane) & 1u)) S.skeep[mi] = 1;
        } else {
            int m0 = (lane < cnt) ? mem[lane] : -1;
            int m1 = (lane + 32 < cnt) ? mem[lane + 32] : -1;
            float4 b0 = make_float4(0.f, 0.f, 0.f, 0.f), b1 = b0;
            float ar0 = 0.f, ar1 = 0.f;
            if (m0 >= 0) {
                float4 t = S.sbox[m0];
                b0 = make_float4(__fadd_rn(t.x, off), __fadd_rn(t.y, off),
                                 __fadd_rn(t.z, off), __fadd_rn(t.w, off));
                ar0 = __fmul_rn(__fsub_rn(b0.z, b0.x), __fsub_rn(b0.w, b0.y));
            }
            if (m1 >= 0) {
                float4 t = S.sbox[m1];
                b1 = make_float4(__fadd_rn(t.x, off), __fadd_rn(t.y, off),
                                 __fadd_rn(t.z, off), __fadd_rn(t.w, off));
                ar1 = __fmul_rn(__fsub_rn(b1.z, b1.x), __fsub_rn(b1.w, b1.y));
            }
            bool sup0 = false, sup1 = false;
            #pragma unroll 1
            for (int i = 0; i < cnt; i++) {
                int d = i >> 5, l = i & 31;
                unsigned sb = __ballot_sync(full, d ? sup1 : sup0);
                bool keep_i = ((sb >> l) & 1u) == 0u;
                if (keep_i) {
                    float bcx = __shfl_sync(full, d ? b1.x : b0.x, l);
                    float bcy = __shfl_sync(full, d ? b1.y : b0.y, l);
                    float bcz = __shfl_sync(full, d ? b1.z : b0.z, l);
                    float bcw = __shfl_sync(full, d ? b1.w : b0.w, l);
                    float ac  = __shfl_sync(full, d ? ar1 : ar0, l);
                    if (m0 >= 0) {
                        float lx = fmaxf(bcx, b0.x), ly = fmaxf(bcy, b0.y);
                        float rx = fminf(bcz, b0.z), ry = fminf(bcw, b0.w);
                        float iw = fmaxf(__fsub_rn(rx, lx), 0.f);
                        float ih = fmaxf(__fsub_rn(ry, ly), 0.f);
                        float inter = __fmul_rn(iw, ih);
                        float den = __fadd_rn(__fsub_rn(__fadd_rn(ac, ar0), inter), 1e-7f);
                        if (__fdiv_rn(inter, den) > IOUT) sup0 = true;
                    }
                    if (m1 >= 0) {
                        float lx = fmaxf(bcx, b1.x), ly = fmaxf(bcy, b1.y);
                        float rx = fminf(bcz, b1.z), ry = fminf(bcw, b1.w);
                        float iw = fmaxf(__fsub_rn(rx, lx), 0.f);
                        float ih = fmaxf(__fsub_rn(ry, ly), 0.f);
                        float inter = __fmul_rn(iw, ih);
                        float den = __fadd_rn(__fsub_rn(__fadd_rn(ac, ar1), inter), 1e-7f);
                        if (__fdiv_rn(inter, den) > IOUT) sup1 = true;
                    }
                    if (lane == l) {
                        if (d) S.skeep[m1] = 1; else S.skeep[m0] = 1;
                    }
                }
            }
        }
    }
    __syncthreads();

    // ===== 5. compact kept candidates + fused min/max of kept keys =====
    int kv2 = S.skeep[tid];
    unsigned bal2 = __ballot_sync(full, kv2 != 0);
    int wpre = __popc(bal2 & lt);
    // warp-local min/max over kept keys (ride the same reduction window)
    unsigned long long kq  = kv2 ? mykey : ~0ull;
    unsigned long long kxv = kv2 ? mykey : 0ull;
    #pragma unroll
    for (int o = 16; o > 0; o >>= 1) {
        unsigned long long t1 = __shfl_xor_sync(full, kq, o);
        unsigned long long t2 = __shfl_xor_sync(full, kxv, o);
        kq  = (t1 < kq)  ? t1 : kq;
        kxv = (t2 > kxv) ? t2 : kxv;
    }
    if (lane == 0) {
        S.wsum[w] = __popc(bal2);
        S.mini[w] = kq;
        S.mini[32 + w] = kxv;
    }
    __syncthreads();
    if (w == 0) {
        int vv = S.wsum[lane], orig = vv;
        #pragma unroll
        for (int o = 1; o < 32; o <<= 1) {
            int t = __shfl_up_sync(full, vv, o);
            if (lane >= o) vv += t;
        }
        S.wsum[lane] = vv - orig;
        if (lane == 31) S.wsum[32] = vv;
        // block min/max + bucket shift
        unsigned long long a = S.mini[lane], b2 = S.mini[32 + lane];
        #pragma unroll
        for (int o = 16; o > 0; o >>= 1) {
            unsigned long long t1 = __shfl_xor_sync(full, a, o);
            unsigned long long t2 = __shfl_xor_sync(full, b2, o);
            a  = (t1 < a)  ? t1 : a;
            b2 = (t2 > b2) ? t2 : b2;
        }
        if (lane == 0) {
            S.s_thr = a;
            unsigned long long range = b2 - a;
            int hb = 63 - __clzll(range | 1ull);
            S.s_b = (hb > 10) ? (hb - 10) : 0;     // (range>>shift) < 2048
        }
    }
    __syncthreads();
    int n_kept = S.wsum[32];
    if (kv2) {
        int pos = S.wsum[w] + wpre;
        S.kkey[pos] = mykey;
        S.kidx[pos] = (short)tid;
    }
    __syncthreads();

    // ===== 6'. exact ranks among kept via monotone bucket-rank (validated r14;
    // hist pre-zeroed by the last resolve, min/max precomputed above) =====
    unsigned long long kmin = S.s_thr;
    int bshift = S.s_b;
    int myb = -1;
    if (tid < n_kept) {
        myb = (int)((S.kkey[tid] - kmin) >> bshift);
        atomicAdd(&S.hist[myb], 1u);               // ~1000 atomics, spread buckets
    }
    __syncthreads();
    {
        unsigned e0 = S.hist[2 * tid], e1 = S.hist[2 * tid + 1];
        unsigned incl = e0 + e1;
        #pragma unroll
        for (int o = 1; o < 32; o <<= 1) {
            unsigned t = __shfl_up_sync(full, incl, o);
            if (lane >= o) incl += t;
        }
        if (lane == 31) S.wtot[w] = incl;
        __syncthreads();
        if (w == 0) {
            unsigned v = S.wtot[lane], iv = v;
            #pragma unroll
            for (int o = 1; o < 32; o <<= 1) {
                unsigned t = __shfl_up_sync(full, iv, o);
                if (lane >= o) iv += t;
            }
            S.wtot[lane] = iv - v;
        }
        __syncthreads();
        unsigned incl1 = S.wtot[w] + incl;
        unsigned excl0 = incl1 - e1 - e0;
        S.cur[2 * tid] = (int)excl0;
        S.cur[2 * tid + 1] = (int)(excl0 + e0);
    }
    __syncthreads();
    int myexcl = 0, mycnt = 0;
    if (myb >= 0) { myexcl = S.cur[myb]; mycnt = (int)S.hist[myb]; }
    __syncthreads();
    if (myb >= 0) {
        int p = atomicAdd(&S.cur[myb], 1);
        S.sorted[p] = S.kkey[tid];
    }
    __syncthreads();
    int grank = -1;
    if (myb >= 0) {
        unsigned long long mk = S.kkey[tid];
        int r = myexcl;
        for (int j = myexcl; j < myexcl + mycnt; j++) r += (S.sorted[j] < mk);
        grank = r;                                  // exact global rank among kept
    }

    // ===== 7'. output =====
    const int OB = 0;
    const int OS = NB * MAXDET * 4;
    const int OL = OS + NB * MAXDET;
    const int OV = OL + NB * MAXDET;

    if (grank >= 0 && grank < MAXDET) {
        int cand = S.kidx[tid];
        unsigned long long wk = S.gath[cand];
        unsigned lo2 = (unsigned)(wk & 0xFFFFFFFFu);
        unsigned hi2 = (unsigned)(wk >> 32);
        unsigned uu = ~hi2;
        unsigned sbits = (uu & 0x80000000u) ? (uu & 0x7FFFFFFFu) : ~uu;
        float4 bx = S.sbox[cand];
        float* ob = out + OB + ((size_t)b * MAXDET + grank) * 4;
        ob[0] = bx.x; ob[1] = bx.y; ob[2] = bx.z; ob[3] = bx.w;
        out[OS + b * MAXDET + grank] = __uint_as_float(sbits);
        out[OL + b * MAXDET + grank] = (float)(lo2 & 127u);
    }
    int n = min(n_kept, MAXDET);
    if (tid < MAXDET) {
        if (tid >= n) {
            float* ob = out + OB + ((size_t)b * MAXDET + tid) * 4;
            ob[0] = 0.f; ob[1] = 0.f; ob[2] = 0.f; ob[3] = 0.f;
            out[OS + b * MAXDET + tid] = 0.f;
            out[OL + b * MAXDET + tid] = -1.f;
        }
        out[OV + b * MAXDET + tid] = (tid < n) ? 1.f : 0.f;
    }
}

// ---------------- launch ----------------
extern "C" void kernel_launch(void* const* d_in, const int* in_sizes, int n_in,
                              void* d_out, int out_size) {
    (void)in_sizes; (void)out_size;
    const float* p0 = (const float*)d_in[0];
    const float* p1 = (const float*)d_in[1];
    const float* p2 = (const float*)d_in[2];
    const int* pH = (n_in > 3) ? (const int*)d_in[3] : nullptr;
    const int* pW = (n_in > 4) ? (const int*)d_in[4] : nullptr;

    cudaFuncSetAttribute(topk_nms_k, cudaFuncAttributeMaxDynamicSharedMemorySize,
                         (int)sizeof(SmemT));
    int tot = NB * NA / 4;
    decode_k<<<(tot + 127) / 128, 128>>>(p0, p1, p2, pH, pW);
    topk_nms_k<<<GRID_PAD, 1024, sizeof(SmemT)>>>((float*)d_out);
}